// round 11
// baseline (speedup 1.0000x reference)
#include <cuda_runtime.h>
#include <cstdint>

// out[b, g, k, c] = textures[b, group_idx[g, k], c]
// B=2, T=1e6, C=16 (fp32), G=500000, K=9.
//
// R11: batch fusion. R2-R10 established the gather L2 hit rate (~43%) and
// DRAM traffic (~940MB) are structural — no cache policy or dispatch order
// moves them. Remaining lever is request economics: both batches share
// group_idx, so one thread now loads each idx ONCE and performs the gather +
// store for batch 0 and batch 1. Halves idx traffic/ops, gives 2 independent
// 32B gathers per thread (128B in flight, R8's depth) at ~30 regs so
// 8 CTAs/SM is kept (R9's occupancy). Loads: LDG.256 L2::evict_last
// (neutral but free). Stores: STG.256 evict-first.

__device__ __forceinline__ void ldg256_evict_last(const float4* p, unsigned long long d[4]) {
    asm volatile("ld.global.nc.L2::evict_last.v4.b64 {%0,%1,%2,%3}, [%4];"
                 : "=l"(d[0]), "=l"(d[1]), "=l"(d[2]), "=l"(d[3])
                 : "l"(p));
}

__device__ __forceinline__ void stg256_cs(float4* p, const unsigned long long d[4]) {
    asm volatile("st.global.cs.v4.b64 [%0], {%1,%2,%3,%4};"
                 :: "l"(p), "l"(d[0]), "l"(d[1]), "l"(d[2]), "l"(d[3]) : "memory");
}

__global__ void __launch_bounds__(256, 8)
tmscnn_gather_kernel(const float4* __restrict__ tex,     // [B, T*C/4]
                     const int*    __restrict__ gidx,    // [G*K]
                     float4*       __restrict__ out,     // [B, G*K*4]
                     int total32,                        // G*K*2 (32B chunks)
                     long long tex_batch_stride_f4,      // T*C/4
                     long long out_batch_stride_f4)      // G*K*4
{
    const int i = blockIdx.x * blockDim.x + threadIdx.x;
    if (i >= total32) return;

    // One idx load serves both batches (group_idx is batch-invariant).
    const int t    = __ldg(gidx + (i >> 1));
    const int half = (i & 1) * 2;
    const long long toff = (long long)t * 4 + half;

    unsigned long long v0[4], v1[4];

    // Two independent 32B gathers (batch 0, batch 1) — MLP 2 per thread,
    // 64 warps/SM -> same chip-level in-flight as R8's best config.
    ldg256_evict_last(tex + toff, v0);
    ldg256_evict_last(tex + tex_batch_stride_f4 + toff, v1);

    // Evict-first streaming stores, one STG.256 per batch.
    float4* dst = out + (long long)i * 2;
    stg256_cs(dst, v0);
    stg256_cs(dst + out_batch_stride_f4, v1);
}

extern "C" void kernel_launch(void* const* d_in, const int* in_sizes, int n_in,
                              void* d_out, int out_size)
{
    // metadata order: mesh_ids [B] int32, textures [B,T,C] f32, group_idx [G,K] int32
    const float* textures = (const float*)d_in[1];
    const int*   gidx     = (const int*)d_in[2];
    float*       out      = (float*)d_out;

    int B  = in_sizes[0];             // 2
    int GK = in_sizes[2];             // G*K = 4,500,000
    long long TC = (long long)in_sizes[1] / B;   // T*C = 16,000,000

    int total32 = GK * 2;             // 9,000,000 32B chunks per batch
    long long tex_stride_f4 = TC / 4; // 4,000,000
    long long out_stride_f4 = (long long)GK * 4;

    dim3 block(256);
    dim3 grid((total32 + 255) / 256);

    tmscnn_gather_kernel<<<grid, block>>>(
        (const float4*)textures, gidx, (float4*)out,
        total32, tex_stride_f4, out_stride_f4);
}

// round 12
// speedup vs baseline: 1.1749x; 1.1749x over previous
#include <cuda_runtime.h>
#include <cstdint>

// out[b, g, k, c] = textures[b, group_idx[g, k], c]
// B=2, T=1e6, C=16 (fp32), G=500000, K=9.
//
// R12: revert R11's batch fusion (it made both 64MB textures live at once,
// overflowing L2: traffic 1.05->1.32GB, 170->204us). grid.y=2 is x-major
// dispatched, i.e. naturally batch-serialized — keep it. New cell in the
// (U, CTAs/SM) grid: U=3 @ __launch_bounds__(256,8).
//   R8: U=3 @ 6 CTAs = 48 warps x 96B in flight -> 163.9us ncu
//   R9: U=2 @ 8 CTAs = 64 warps x 64B          -> 164.9us ncu
//   here: 64 warps x 96B (+33% in-flight reads). R11 showed the DRAM can
//   sustain 6.7TB/s when more misses are queued. ~32 regs should just fit;
//   spill (STL/LDL) is the failure mode.

#define U 3

__device__ __forceinline__ void ldg256_evict_last(const float4* p, unsigned long long d[4]) {
    asm volatile("ld.global.nc.L2::evict_last.v4.b64 {%0,%1,%2,%3}, [%4];"
                 : "=l"(d[0]), "=l"(d[1]), "=l"(d[2]), "=l"(d[3])
                 : "l"(p));
}

__device__ __forceinline__ void stg256_cs(float4* p, const unsigned long long d[4]) {
    asm volatile("st.global.cs.v4.b64 [%0], {%1,%2,%3,%4};"
                 :: "l"(p), "l"(d[0]), "l"(d[1]), "l"(d[2]), "l"(d[3]) : "memory");
}

__global__ void __launch_bounds__(256, 8)
tmscnn_gather_kernel(const float4* __restrict__ tex,     // [B, T*C/4]
                     const int*    __restrict__ gidx,    // [G*K]
                     float4*       __restrict__ out,     // [B, G*K*4]
                     int total32,                        // G*K*2 (32B chunks)
                     long long tex_batch_stride_f4,      // T*C/4
                     long long out_batch_stride_f4)      // G*K*4
{
    const int stride = gridDim.x * blockDim.x;
    const int i0 = blockIdx.x * blockDim.x + threadIdx.x;
    const int b = blockIdx.y;

    const float4* tex_b = tex + (long long)b * tex_batch_stride_f4;
    float4*       out_b = out + (long long)b * out_batch_stride_f4;

    int ii[U];
    int tt[U];
    unsigned long long vv[U][4];

    // Phase 1: independent index loads (2 lanes share one idx)
    #pragma unroll
    for (int u = 0; u < U; u++) {
        ii[u] = i0 + u * stride;
        tt[u] = 0;
        if (ii[u] < total32)
            tt[u] = __ldg(gidx + (ii[u] >> 1));
    }

    // Phase 2: independent 32B gathers, LDG.256 with L2 evict_last
    #pragma unroll
    for (int u = 0; u < U; u++) {
        if (ii[u] < total32) {
            const float4* src = tex_b + (long long)tt[u] * 4 + (ii[u] & 1) * 2;
            ldg256_evict_last(src, vv[u]);
        }
    }

    // Phase 3: evict-first streaming stores, one STG.256 per chunk
    #pragma unroll
    for (int u = 0; u < U; u++) {
        if (ii[u] < total32)
            stg256_cs(out_b + (long long)ii[u] * 2, vv[u]);
    }
}

extern "C" void kernel_launch(void* const* d_in, const int* in_sizes, int n_in,
                              void* d_out, int out_size)
{
    // metadata order: mesh_ids [B] int32, textures [B,T,C] f32, group_idx [G,K] int32
    const float* textures = (const float*)d_in[1];
    const int*   gidx     = (const int*)d_in[2];
    float*       out      = (float*)d_out;

    int B  = in_sizes[0];             // 2
    int GK = in_sizes[2];             // G*K = 4,500,000
    long long TC = (long long)in_sizes[1] / B;   // T*C = 16,000,000

    int total32 = GK * 2;             // 9,000,000 32B chunks per batch
    long long tex_stride_f4 = TC / 4; // 4,000,000
    long long out_stride_f4 = (long long)GK * 4;

    int threads_needed = (total32 + U - 1) / U;
    dim3 block(256);
    dim3 grid((threads_needed + 255) / 256, B);

    tmscnn_gather_kernel<<<grid, block>>>(
        (const float4*)textures, gidx, (float4*)out,
        total32, tex_stride_f4, out_stride_f4);
}

// round 13
// speedup vs baseline: 1.1991x; 1.0206x over previous
#include <cuda_runtime.h>
#include <cstdint>

// out[b, g, k, c] = textures[b, group_idx[g, k], c]
// B=2, T=1e6, C=16 (fp32), G=500000, K=9.
//
// R13: R8 config (bench-best, 170.0us; U=3 @ 6 CTAs/SM, LDG.256 evict_last,
// STG.256 .cs, grid.y=2) + wave-rounded grid. Evidence-consolidated model:
//  - in-flight depth plateau: 3.4-4.6KB/SM all give ~164us ncu; extremes worse
//    (R7 177.8, R12 169.6 — the latter from reg-cap-induced MLP loss at 32 regs)
//  - read traffic (~460MB vs 128MB compulsory) is structural: .cs/.wt/
//    evict_last/batch-serialization all inert; L2 carveout is blocked by the
//    harness device-limit guard
// Tweak: blocks_per_batch rounded up to full waves (888 blocks = 148 SM x 6)
// so batch tails don't leave a 20%-populated straggler wave. Excess threads
// exit via the existing bounds guard.

#define U 3

__device__ __forceinline__ void ldg256_evict_last(const float4* p, unsigned long long d[4]) {
    asm volatile("ld.global.nc.L2::evict_last.v4.b64 {%0,%1,%2,%3}, [%4];"
                 : "=l"(d[0]), "=l"(d[1]), "=l"(d[2]), "=l"(d[3])
                 : "l"(p));
}

__device__ __forceinline__ void stg256_cs(float4* p, const unsigned long long d[4]) {
    asm volatile("st.global.cs.v4.b64 [%0], {%1,%2,%3,%4};"
                 :: "l"(p), "l"(d[0]), "l"(d[1]), "l"(d[2]), "l"(d[3]) : "memory");
}

__global__ void __launch_bounds__(256, 6)
tmscnn_gather_kernel(const float4* __restrict__ tex,     // [B, T*C/4]
                     const int*    __restrict__ gidx,    // [G*K]
                     float4*       __restrict__ out,     // [B, G*K*4]
                     int total32,                        // G*K*2 (32B chunks)
                     long long tex_batch_stride_f4,      // T*C/4
                     long long out_batch_stride_f4)      // G*K*4
{
    const int stride = gridDim.x * blockDim.x;
    const int i0 = blockIdx.x * blockDim.x + threadIdx.x;
    const int b = blockIdx.y;

    const float4* tex_b = tex + (long long)b * tex_batch_stride_f4;
    float4*       out_b = out + (long long)b * out_batch_stride_f4;

    int ii[U];
    int tt[U];
    unsigned long long vv[U][4];

    // Phase 1: independent index loads (2 lanes share one idx)
    #pragma unroll
    for (int u = 0; u < U; u++) {
        ii[u] = i0 + u * stride;
        tt[u] = 0;
        if (ii[u] < total32)
            tt[u] = __ldg(gidx + (ii[u] >> 1));
    }

    // Phase 2: independent 32B gathers, LDG.256 with L2 evict_last
    #pragma unroll
    for (int u = 0; u < U; u++) {
        if (ii[u] < total32) {
            const float4* src = tex_b + (long long)tt[u] * 4 + (ii[u] & 1) * 2;
            ldg256_evict_last(src, vv[u]);
        }
    }

    // Phase 3: evict-first streaming stores, one STG.256 per chunk
    #pragma unroll
    for (int u = 0; u < U; u++) {
        if (ii[u] < total32)
            stg256_cs(out_b + (long long)ii[u] * 2, vv[u]);
    }
}

extern "C" void kernel_launch(void* const* d_in, const int* in_sizes, int n_in,
                              void* d_out, int out_size)
{
    // metadata order: mesh_ids [B] int32, textures [B,T,C] f32, group_idx [G,K] int32
    const float* textures = (const float*)d_in[1];
    const int*   gidx     = (const int*)d_in[2];
    float*       out      = (float*)d_out;

    int B  = in_sizes[0];             // 2
    int GK = in_sizes[2];             // G*K = 4,500,000
    long long TC = (long long)in_sizes[1] / B;   // T*C = 16,000,000

    int total32 = GK * 2;             // 9,000,000 32B chunks per batch
    long long tex_stride_f4 = TC / 4; // 4,000,000
    long long out_stride_f4 = (long long)GK * 4;

    int threads_needed = (total32 + U - 1) / U;
    int blocks_per_batch = (threads_needed + 255) / 256;

    // Round up to whole waves: 148 SMs x 6 CTAs/SM = 888 blocks per wave.
    const int wave = 148 * 6;
    blocks_per_batch = ((blocks_per_batch + wave - 1) / wave) * wave;

    dim3 block(256);
    dim3 grid(blocks_per_batch, B);

    tmscnn_gather_kernel<<<grid, block>>>(
        (const float4*)textures, gidx, (float4*)out,
        total32, tex_stride_f4, out_stride_f4);
}